// round 15
// baseline (speedup 1.0000x reference)
#include <cuda_runtime.h>
#include <cuda_fp16.h>
#include <math.h>
#include <stdint.h>

#define NN 20000
#define EE 320000
#define ET 340000      // EE + NN self loops
#define FIN 128
#define D1 512         // HEADS*HID
#define HEADS 8
#define HID 64
#define NC 10
#define NG 64
#define NB ((NN + 255) / 256)   // 79 scan blocks
#define LOG2E 1.4426950408889634f

// -------- scratch (device globals; no allocations allowed) --------
__device__ __half g_h1h[(size_t)NN * D1];    // layer1 features fp16
__device__ __half g_h1act[(size_t)NN * D1];  // elu(agg1 + b1), fp16
__device__ __half g_xh[(size_t)NN * FIN];    // x in fp16
__device__ __half g_w1h[FIN * D1];           // W1 in fp16
__device__ float  g_asrc1[NN * HEADS];
__device__ float  g_adst1[NN * HEADS];
__device__ __half g_ewh[(size_t)ET * HEADS]; // per-(edge,head) weights, fp16
__device__ float  g_h2[NN * NC];
__device__ float  g_asrc2[NN];
__device__ float  g_adst2[NN];
__device__ float  g_agg2[NN * NC];
__device__ int    g_counts[NN];   // zero-init; scanC resets to 0 each call
__device__ int    g_rowptr[NN + 1];
__device__ int    g_wptr[NN];
__device__ int    g_csrc[ET];
__device__ int    g_bsum[NB];
__device__ int    g_boff[NB];

struct alignas(8) H4 { __half2 a, b; };   // 4 halfs, one LDG/STG.64

__device__ __forceinline__ float wredsum(float v) {
    #pragma unroll
    for (int o = 16; o; o >>= 1) v += __shfl_xor_sync(0xffffffffu, v, o);
    return v;
}
__device__ __forceinline__ uint32_t sptr(const void* p) {
    return (uint32_t)__cvta_generic_to_shared(p);
}
// exp(a),exp(b) -> packed half2 (one MUFU op for two exps)
__device__ __forceinline__ uint32_t exp2_h2(float a, float b) {
    union { __half2 h; uint32_t u; } in, out;
    in.h = __floats2half2_rn(a * LOG2E, b * LOG2E);
    asm("ex2.approx.f16x2 %0, %1;" : "=r"(out.u) : "r"(in.u));
    return out.u;
}
__device__ __forceinline__ float lrelu(float v) {
    return v > 0.f ? v : 0.2f * v;
}

// -------- prep: x->fp16, W1->fp16, degree count --------
__global__ void prep_kernel(const float* __restrict__ X,
                            const float* __restrict__ W,
                            const int* __restrict__ ei) {
    int i = blockIdx.x * 256 + threadIdx.x;
    if (i < NN * FIN / 4) {
        float4 v = ((const float4*)X)[i];
        H4 pk;
        pk.a = __floats2half2_rn(v.x, v.y);
        pk.b = __floats2half2_rn(v.z, v.w);
        ((H4*)g_xh)[i] = pk;
    }
    if (i < FIN * D1 / 4) {
        float4 v = ((const float4*)W)[i];
        H4 pk;
        pk.a = __floats2half2_rn(v.x, v.y);
        pk.b = __floats2half2_rn(v.z, v.w);
        ((H4*)g_w1h)[i] = pk;
    }
    if (i < EE / 4) {
        int4 d = ((const int4*)(ei + EE))[i];
        atomicAdd(&g_counts[d.x], 1);
        atomicAdd(&g_counts[d.y], 1);
        atomicAdd(&g_counts[d.z], 1);
        atomicAdd(&g_counts[d.w], 1);
    }
}

// -------- scan phase A: per-block exclusive scan of (counts+1) --------
__global__ void scanA_kernel() {
    __shared__ int sh[256];
    int t = threadIdx.x;
    int n = blockIdx.x * 256 + t;
    int c = (n < NN) ? (g_counts[n] + 1) : 0;   // +1 = self loop
    sh[t] = c;
    __syncthreads();
    #pragma unroll
    for (int off = 1; off < 256; off <<= 1) {
        int v = (t >= off) ? sh[t - off] : 0;
        __syncthreads();
        sh[t] += v;
        __syncthreads();
    }
    if (n < NN) g_rowptr[n] = sh[t] - c;
    if (t == 255) g_bsum[blockIdx.x] = sh[255];
}
// phase B: single block scans block sums
__global__ void scanB_kernel() {
    __shared__ int sh[128];
    int t = threadIdx.x;
    int v = (t < NB) ? g_bsum[t] : 0;
    sh[t] = v;
    __syncthreads();
    #pragma unroll
    for (int off = 1; off < 128; off <<= 1) {
        int u = (t >= off) ? sh[t - off] : 0;
        __syncthreads();
        sh[t] += u;
        __syncthreads();
    }
    if (t < NB) g_boff[t] = sh[t] - v;
}
// phase C: globalize rowptr, seed self-loop slot + its weights, reset counts
__global__ void scanC_kernel() {
    int n = blockIdx.x * blockDim.x + threadIdx.x;
    if (n >= NN) return;
    int r = g_rowptr[n] + g_boff[n >> 8];
    g_rowptr[n] = r;
    g_wptr[n] = r + 1;
    g_csrc[r] = n;
    g_counts[n] = 0;   // ready for next graph replay
    float4 s0 = *(const float4*)&g_asrc1[n * 8];
    float4 s1 = *(const float4*)&g_asrc1[n * 8 + 4];
    float4 d0 = *(const float4*)&g_adst1[n * 8];
    float4 d1 = *(const float4*)&g_adst1[n * 8 + 4];
    uint4 w;
    w.x = exp2_h2(lrelu(s0.x + d0.x), lrelu(s0.y + d0.y));
    w.y = exp2_h2(lrelu(s0.z + d0.z), lrelu(s0.w + d0.w));
    w.z = exp2_h2(lrelu(s1.x + d1.x), lrelu(s1.y + d1.y));
    w.w = exp2_h2(lrelu(s1.z + d1.z), lrelu(s1.w + d1.w));
    *(uint4*)&g_ewh[(size_t)r * 8] = w;
    if (n == 0) g_rowptr[NN] = ET;
}

// -------- scatter + fused edge weights --------
__global__ void scatter_ew_kernel(const int* __restrict__ ei) {
    int i = blockIdx.x * blockDim.x + threadIdx.x;
    if (i >= EE / 4) return;
    int4 s = ((const int4*)ei)[i];
    int4 d = ((const int4*)(ei + EE))[i];
    int src[4] = {s.x, s.y, s.z, s.w};
    int dst[4] = {d.x, d.y, d.z, d.w};
    #pragma unroll
    for (int k = 0; k < 4; k++) {
        int p = atomicAdd(&g_wptr[dst[k]], 1);
        g_csrc[p] = src[k];
        float4 s0 = *(const float4*)&g_asrc1[src[k] * 8];
        float4 s1 = *(const float4*)&g_asrc1[src[k] * 8 + 4];
        float4 d0 = *(const float4*)&g_adst1[dst[k] * 8];
        float4 d1 = *(const float4*)&g_adst1[dst[k] * 8 + 4];
        uint4 w;
        w.x = exp2_h2(lrelu(s0.x + d0.x), lrelu(s0.y + d0.y));
        w.y = exp2_h2(lrelu(s0.z + d0.z), lrelu(s0.w + d0.w));
        w.z = exp2_h2(lrelu(s1.x + d1.x), lrelu(s1.y + d1.y));
        w.w = exp2_h2(lrelu(s1.z + d1.z), lrelu(s1.w + d1.w));
        *(uint4*)&g_ewh[(size_t)p * 8] = w;
    }
}

// -------- tensor-core GEMM1 + fused attention coefs (single-phase loads) --------
__global__ __launch_bounds__(256, 2)
void gemm1_tc_kernel(const float* __restrict__ asv,
                     const float* __restrict__ adv) {
    __shared__ __half Xs[128][136];  // full K=128, pad 8: LDSM conflict-free
    __shared__ __half Ws[128][72];   // full K rows x 64 cols
    __shared__ float sa[64], sd[64];
    int t = threadIdx.x, lane = t & 31, wid = t >> 5;
    int nb = blockIdx.x;             // head / 64-col block
    int mb = blockIdx.y;
    int mB = mb * 128;
    if (t < 64) { sa[t] = asv[nb * 64 + t]; sd[t] = adv[nb * 64 + t]; }

    #pragma unroll
    for (int p = 0; p < 8; p++) {
        int idx = t + p * 256;           // 0..2047
        int row = idx >> 4, ch = idx & 15;
        int grow = mB + row;
        uint4 v = make_uint4(0u, 0u, 0u, 0u);
        if (grow < NN)
            v = *(const uint4*)&g_xh[(size_t)grow * FIN + ch * 8];
        *(uint4*)&Xs[row][ch * 8] = v;
    }
    #pragma unroll
    for (int p = 0; p < 4; p++) {
        int idx = t + p * 256;           // 0..1023
        int row = idx >> 3, ch = idx & 7;
        uint4 v = *(const uint4*)&g_w1h[(size_t)row * D1 + nb * 64 + ch * 8];
        *(uint4*)&Ws[row][ch * 8] = v;
    }
    __syncthreads();

    float acc[8][4];
    #pragma unroll
    for (int i = 0; i < 8; i++)
        #pragma unroll
        for (int j = 0; j < 4; j++) acc[i][j] = 0.f;

    #pragma unroll
    for (int ks = 0; ks < 8; ks++) {
        int k0 = ks * 16;
        uint32_t a0, a1, a2, a3;
        {
            uint32_t ad = sptr(&Xs[wid * 16 + (lane & 15)][k0 + ((lane & 16) ? 8 : 0)]);
            asm volatile(
                "ldmatrix.sync.aligned.m8n8.x4.shared.b16 {%0,%1,%2,%3}, [%4];"
                : "=r"(a0), "=r"(a1), "=r"(a2), "=r"(a3) : "r"(ad));
        }
        #pragma unroll
        for (int ntp = 0; ntp < 4; ntp++) {
            uint32_t b0, b1, b2, b3;
            uint32_t bd = sptr(&Ws[k0 + (lane & 15)][ntp * 16 + ((lane & 16) ? 8 : 0)]);
            asm volatile(
                "ldmatrix.sync.aligned.m8n8.x4.trans.shared.b16 {%0,%1,%2,%3}, [%4];"
                : "=r"(b0), "=r"(b1), "=r"(b2), "=r"(b3) : "r"(bd));
            asm volatile(
                "mma.sync.aligned.m16n8k16.row.col.f32.f16.f16.f32 "
                "{%0,%1,%2,%3}, {%4,%5,%6,%7}, {%8,%9}, {%0,%1,%2,%3};"
                : "+f"(acc[2 * ntp][0]), "+f"(acc[2 * ntp][1]),
                  "+f"(acc[2 * ntp][2]), "+f"(acc[2 * ntp][3])
                : "r"(a0), "r"(a1), "r"(a2), "r"(a3), "r"(b0), "r"(b1));
            asm volatile(
                "mma.sync.aligned.m16n8k16.row.col.f32.f16.f16.f32 "
                "{%0,%1,%2,%3}, {%4,%5,%6,%7}, {%8,%9}, {%0,%1,%2,%3};"
                : "+f"(acc[2 * ntp + 1][0]), "+f"(acc[2 * ntp + 1][1]),
                  "+f"(acc[2 * ntp + 1][2]), "+f"(acc[2 * ntp + 1][3])
                : "r"(a0), "r"(a1), "r"(a2), "r"(a3), "r"(b2), "r"(b3));
        }
    }

    // epilogue: store h1 fp16 + complete per-head coefs (BN==HID)
    int rlo = mB + wid * 16 + (lane >> 2);
    int rhi = rlo + 8;
    int q = lane & 3;
    float slo = 0.f, shi = 0.f, dlo = 0.f, dhi = 0.f;
    #pragma unroll
    for (int nt = 0; nt < 8; nt++) {
        int c = nt * 8 + 2 * q;
        slo += acc[nt][0] * sa[c] + acc[nt][1] * sa[c + 1];
        dlo += acc[nt][0] * sd[c] + acc[nt][1] * sd[c + 1];
        shi += acc[nt][2] * sa[c] + acc[nt][3] * sa[c + 1];
        dhi += acc[nt][2] * sd[c] + acc[nt][3] * sd[c + 1];
        if (rlo < NN)
            *(__half2*)&g_h1h[(size_t)rlo * D1 + nb * 64 + c] =
                __floats2half2_rn(acc[nt][0], acc[nt][1]);
        if (rhi < NN)
            *(__half2*)&g_h1h[(size_t)rhi * D1 + nb * 64 + c] =
                __floats2half2_rn(acc[nt][2], acc[nt][3]);
    }
    #pragma unroll
    for (int o = 1; o <= 2; o <<= 1) {
        slo += __shfl_xor_sync(0xffffffffu, slo, o);
        dlo += __shfl_xor_sync(0xffffffffu, dlo, o);
        shi += __shfl_xor_sync(0xffffffffu, shi, o);
        dhi += __shfl_xor_sync(0xffffffffu, dhi, o);
    }
    if (q == 0) {
        if (rlo < NN) { g_asrc1[rlo * 8 + nb] = slo; g_adst1[rlo * 8 + nb] = dlo; }
        if (rhi < NN) { g_asrc1[rhi * 8 + nb] = shi; g_adst1[rhi * 8 + nb] = dhi; }
    }
}

// -------- layer-1 aggregation: shuffle-batched, barrier-free --------
// 2 nodes per 256-thread block; thread t owns channels 4t..4t+3.
// Warp w (of node) covers heads {2w, 2w+1}; per 32-edge batch it issues TWO
// coalesced LDGs (indices + weight half2s), then per edge: shfl + one LDG.64.
__global__ void agg1_kernel(const float* __restrict__ b1) {
    int tt = threadIdx.x;
    int t = tt & 127;
    int d = blockIdx.x * 2 + (tt >> 7);   // NN even
    int lane = t & 31;
    int w = t >> 5;                       // warp within node: heads 2w, 2w+1
    int beg = g_rowptr[d];
    int deg = g_rowptr[d + 1] - beg;
    float ax = 0.f, ay = 0.f, az = 0.f, aw = 0.f, wsum = 0.f;

    for (int base = 0; base < deg; base += 32) {
        int cn = min(32, deg - base);
        int sn_r = 0;
        uint32_t ew_r = 0u;
        if (lane < cn) {
            int e = beg + base + lane;
            sn_r = g_csrc[e];
            ew_r = *(const uint32_t*)&g_ewh[(size_t)e * 8 + 2 * w];
        }
        #pragma unroll 4
        for (int i = 0; i < cn; i++) {
            int sn = __shfl_sync(0xffffffffu, sn_r, i);
            uint32_t wu = __shfl_sync(0xffffffffu, ew_r, i);
            union { uint32_t u; __half2 h; } cv;
            cv.u = wu;
            float2 wf = __half22float2(cv.h);
            float a = (t & 16) ? wf.y : wf.x;     // head 2w vs 2w+1
            H4 v = *(const H4*)&g_h1h[(size_t)sn * D1 + 4 * t];
            float2 f0 = __half22float2(v.a);
            float2 f1 = __half22float2(v.b);
            ax += a * f0.x; ay += a * f0.y;
            az += a * f1.x; aw += a * f1.y;
            wsum += a;
        }
    }
    float inv = 1.f / (wsum + 1e-16f);
    float4 bv = *(const float4*)&b1[4 * t];
    float o0, o1, o2, o3;
    o0 = ax * inv + bv.x; o0 = o0 > 0.f ? o0 : expm1f(o0);
    o1 = ay * inv + bv.y; o1 = o1 > 0.f ? o1 : expm1f(o1);
    o2 = az * inv + bv.z; o2 = o2 > 0.f ? o2 : expm1f(o2);
    o3 = aw * inv + bv.w; o3 = o3 > 0.f ? o3 : expm1f(o3);
    H4 pk;
    pk.a = __floats2half2_rn(o0, o1);
    pk.b = __floats2half2_rn(o2, o3);
    *(H4*)&g_h1act[(size_t)d * D1 + 4 * t] = pk;
}

// -------- layer 2 GEMV + coefficients (warp per node, transposed W2 smem) --------
__global__ void node2_kernel(const float* __restrict__ W2,
                             const float* __restrict__ as2,
                             const float* __restrict__ ad2) {
    __shared__ float Ws[NC * D1];   // [j][c] transposed
    __shared__ float sas[NC], sad[NC];
    int t = threadIdx.x;
    for (int i = t; i < D1 * NC; i += 256) {
        int c = i / NC, j = i - c * NC;
        Ws[j * D1 + c] = W2[i];
    }
    if (t < NC) { sas[t] = as2[t]; sad[t] = ad2[t]; }
    __syncthreads();
    int n = blockIdx.x * 8 + (t >> 5);
    if (n >= NN) return;
    int lane = t & 31;
    const __half* hp = &g_h1act[(size_t)n * D1];
    float acc[NC];
    #pragma unroll
    for (int j = 0; j < NC; j++) acc[j] = 0.f;
    for (int c = lane; c < D1; c += 32) {
        float xv = __half2float(hp[c]);
        #pragma unroll
        for (int j = 0; j < NC; j++) acc[j] += xv * Ws[j * D1 + c];
    }
    #pragma unroll
    for (int j = 0; j < NC; j++) acc[j] = wredsum(acc[j]);
    if (lane == 0) {
        float s = 0.f, dd = 0.f;
        #pragma unroll
        for (int j = 0; j < NC; j++) {
            g_h2[n * NC + j] = acc[j];
            s  += acc[j] * sas[j];
            dd += acc[j] * sad[j];
        }
        g_asrc2[n] = s;
        g_adst2[n] = dd;
    }
}

// -------- layer-2 edge softmax + aggregation (warp per dst, single pass) --------
__global__ void agg2_kernel(const float* __restrict__ b2) {
    int n = blockIdx.x * 8 + (threadIdx.x >> 5);
    if (n >= NN) return;
    int lane = threadIdx.x & 31;
    int beg = g_rowptr[n], end = g_rowptr[n + 1];
    float adv = g_adst2[n];
    float s = 0.f;
    float acc[NC];
    #pragma unroll
    for (int j = 0; j < NC; j++) acc[j] = 0.f;
    for (int i = beg + lane; i < end; i += 32) {
        int sn = g_csrc[i];
        float e = g_asrc2[sn] + adv;
        e = e > 0.f ? e : 0.2f * e;
        float w = __expf(e);
        s += w;
        const float* hp = &g_h2[sn * NC];
        #pragma unroll
        for (int j = 0; j < NC; j++) acc[j] += w * hp[j];
    }
    s = wredsum(s);
    #pragma unroll
    for (int j = 0; j < NC; j++) acc[j] = wredsum(acc[j]);
    if (lane == 0) {
        float inv = 1.f / (s + 1e-16f);
        #pragma unroll
        for (int j = 0; j < NC; j++)
            g_agg2[n * NC + j] = acc[j] * inv + b2[j];
    }
}

// -------- mean pooling per graph (batch is sorted) --------
__global__ void pool_kernel(const int* __restrict__ batch,
                            float* __restrict__ out) {
    int g = blockIdx.x;
    int t = threadIdx.x;
    int lo, hi;
    { int a = 0, b = NN;
      while (a < b) { int mid = (a + b) >> 1; if (batch[mid] < g) a = mid + 1; else b = mid; }
      lo = a; }
    { int a = lo, b = NN;
      while (a < b) { int mid = (a + b) >> 1; if (batch[mid] < g + 1) a = mid + 1; else b = mid; }
      hi = a; }
    __shared__ float red[NC];
    if (t < NC) red[t] = 0.f;
    __syncthreads();
    float acc[NC];
    #pragma unroll
    for (int j = 0; j < NC; j++) acc[j] = 0.f;
    for (int i = lo + t; i < hi; i += 256) {
        const float* hp = &g_agg2[i * NC];
        #pragma unroll
        for (int j = 0; j < NC; j++) acc[j] += hp[j];
    }
    #pragma unroll
    for (int j = 0; j < NC; j++) atomicAdd(&red[j], acc[j]);
    __syncthreads();
    int cnt = hi - lo;
    if (cnt < 1) cnt = 1;
    if (t < NC) out[g * NC + t] = red[t] / (float)cnt;
}

// -------- launcher (gemm1_tc at launch idx 3 for profiling) --------
extern "C" void kernel_launch(void* const* d_in, const int* in_sizes, int n_in,
                              void* d_out, int out_size) {
    const float* x   = (const float*)d_in[0];
    const int*   ei  = (const int*)d_in[1];
    const int*   bat = (const int*)d_in[2];
    const float* W1  = (const float*)d_in[3];
    const float* as1 = (const float*)d_in[4];
    const float* ad1 = (const float*)d_in[5];
    const float* b1  = (const float*)d_in[6];
    const float* W2  = (const float*)d_in[7];
    const float* as2 = (const float*)d_in[8];
    const float* ad2 = (const float*)d_in[9];
    const float* b2  = (const float*)d_in[10];
    float* out = (float*)d_out;

    prep_kernel<<<(NN * FIN / 4 + 255) / 256, 256>>>(x, W1, ei);
    scanA_kernel<<<NB, 256>>>();
    scanB_kernel<<<1, 128>>>();
    gemm1_tc_kernel<<<dim3(HEADS, (NN + 127) / 128), 256>>>(as1, ad1);
    scanC_kernel<<<(NN + 255) / 256, 256>>>();
    scatter_ew_kernel<<<(EE / 4 + 255) / 256, 256>>>(ei);

    agg1_kernel<<<NN / 2, 256>>>(b1);

    node2_kernel<<<(NN + 7) / 8, 256>>>(W2, as2, ad2);
    agg2_kernel<<<(NN + 7) / 8, 256>>>(b2);
    pool_kernel<<<NG, 256>>>(bat, out);
}

// round 17
// speedup vs baseline: 1.0894x; 1.0894x over previous
#include <cuda_runtime.h>
#include <cuda_fp16.h>
#include <math.h>
#include <stdint.h>

#define NN 20000
#define EE 320000
#define ET 340000      // EE + NN self loops
#define FIN 128
#define D1 512         // HEADS*HID
#define HEADS 8
#define HID 64
#define NC 10
#define NG 64
#define NB ((NN + 255) / 256)   // 79 scan blocks
#define LOG2E 1.4426950408889634f

// -------- scratch (device globals; no allocations allowed) --------
__device__ __half g_h1h[(size_t)NN * D1];    // layer1 features fp16
__device__ __half g_h1act[(size_t)NN * D1];  // elu(agg1 + b1), fp16
__device__ __half g_xh[(size_t)NN * FIN];    // x in fp16
__device__ __half g_w1h[FIN * D1];           // W1 in fp16
__device__ float  g_asrc1[NN * HEADS];
__device__ float  g_adst1[NN * HEADS];
__device__ __half g_ewh[(size_t)ET * HEADS]; // per-(edge,head) weights, fp16
__device__ float  g_h2[NN * NC];
__device__ float  g_asrc2[NN];
__device__ float  g_adst2[NN];
__device__ float  g_agg2[NN * NC];
__device__ int    g_counts[NN];   // zero-init; scanC resets to 0 each call
__device__ int    g_rowptr[NN + 1];
__device__ int    g_wptr[NN];
__device__ int    g_csrc[ET];
__device__ int    g_bsum[NB];
__device__ int    g_boff[NB];

struct alignas(8) H4 { __half2 a, b; };   // 4 halfs, one LDG/STG.64

__device__ __forceinline__ float wredsum(float v) {
    #pragma unroll
    for (int o = 16; o; o >>= 1) v += __shfl_xor_sync(0xffffffffu, v, o);
    return v;
}
__device__ __forceinline__ uint32_t sptr(const void* p) {
    return (uint32_t)__cvta_generic_to_shared(p);
}
// exp(a),exp(b) -> packed half2 (one MUFU op for two exps)
__device__ __forceinline__ uint32_t exp2_h2(float a, float b) {
    union { __half2 h; uint32_t u; } in, out;
    in.h = __floats2half2_rn(a * LOG2E, b * LOG2E);
    asm("ex2.approx.f16x2 %0, %1;" : "=r"(out.u) : "r"(in.u));
    return out.u;
}
__device__ __forceinline__ float lrelu(float v) {
    return v > 0.f ? v : 0.2f * v;
}

// -------- prep: x->fp16, W1->fp16, degree count --------
__global__ void prep_kernel(const float* __restrict__ X,
                            const float* __restrict__ W,
                            const int* __restrict__ ei) {
    int i = blockIdx.x * 256 + threadIdx.x;
    if (i < NN * FIN / 4) {
        float4 v = ((const float4*)X)[i];
        H4 pk;
        pk.a = __floats2half2_rn(v.x, v.y);
        pk.b = __floats2half2_rn(v.z, v.w);
        ((H4*)g_xh)[i] = pk;
    }
    if (i < FIN * D1 / 4) {
        float4 v = ((const float4*)W)[i];
        H4 pk;
        pk.a = __floats2half2_rn(v.x, v.y);
        pk.b = __floats2half2_rn(v.z, v.w);
        ((H4*)g_w1h)[i] = pk;
    }
    if (i < EE / 4) {
        int4 d = ((const int4*)(ei + EE))[i];
        atomicAdd(&g_counts[d.x], 1);
        atomicAdd(&g_counts[d.y], 1);
        atomicAdd(&g_counts[d.z], 1);
        atomicAdd(&g_counts[d.w], 1);
    }
}

// -------- scan phase A: per-block exclusive scan of (counts+1) --------
__global__ void scanA_kernel() {
    __shared__ int sh[256];
    int t = threadIdx.x;
    int n = blockIdx.x * 256 + t;
    int c = (n < NN) ? (g_counts[n] + 1) : 0;   // +1 = self loop
    sh[t] = c;
    __syncthreads();
    #pragma unroll
    for (int off = 1; off < 256; off <<= 1) {
        int v = (t >= off) ? sh[t - off] : 0;
        __syncthreads();
        sh[t] += v;
        __syncthreads();
    }
    if (n < NN) g_rowptr[n] = sh[t] - c;
    if (t == 255) g_bsum[blockIdx.x] = sh[255];
}
// phase B: single block scans block sums
__global__ void scanB_kernel() {
    __shared__ int sh[128];
    int t = threadIdx.x;
    int v = (t < NB) ? g_bsum[t] : 0;
    sh[t] = v;
    __syncthreads();
    #pragma unroll
    for (int off = 1; off < 128; off <<= 1) {
        int u = (t >= off) ? sh[t - off] : 0;
        __syncthreads();
        sh[t] += u;
        __syncthreads();
    }
    if (t < NB) g_boff[t] = sh[t] - v;
}
// phase C: globalize rowptr, seed self-loop slot + its weights, reset counts
__global__ void scanC_kernel() {
    int n = blockIdx.x * blockDim.x + threadIdx.x;
    if (n >= NN) return;
    int r = g_rowptr[n] + g_boff[n >> 8];
    g_rowptr[n] = r;
    g_wptr[n] = r + 1;
    g_csrc[r] = n;
    g_counts[n] = 0;   // ready for next graph replay
    float4 s0 = *(const float4*)&g_asrc1[n * 8];
    float4 s1 = *(const float4*)&g_asrc1[n * 8 + 4];
    float4 d0 = *(const float4*)&g_adst1[n * 8];
    float4 d1 = *(const float4*)&g_adst1[n * 8 + 4];
    uint4 w;
    w.x = exp2_h2(lrelu(s0.x + d0.x), lrelu(s0.y + d0.y));
    w.y = exp2_h2(lrelu(s0.z + d0.z), lrelu(s0.w + d0.w));
    w.z = exp2_h2(lrelu(s1.x + d1.x), lrelu(s1.y + d1.y));
    w.w = exp2_h2(lrelu(s1.z + d1.z), lrelu(s1.w + d1.w));
    *(uint4*)&g_ewh[(size_t)r * 8] = w;
    if (n == 0) g_rowptr[NN] = ET;
}

// -------- scatter + fused edge weights --------
__global__ void scatter_ew_kernel(const int* __restrict__ ei) {
    int i = blockIdx.x * blockDim.x + threadIdx.x;
    if (i >= EE / 4) return;
    int4 s = ((const int4*)ei)[i];
    int4 d = ((const int4*)(ei + EE))[i];
    int src[4] = {s.x, s.y, s.z, s.w};
    int dst[4] = {d.x, d.y, d.z, d.w};
    #pragma unroll
    for (int k = 0; k < 4; k++) {
        int p = atomicAdd(&g_wptr[dst[k]], 1);
        g_csrc[p] = src[k];
        float4 s0 = *(const float4*)&g_asrc1[src[k] * 8];
        float4 s1 = *(const float4*)&g_asrc1[src[k] * 8 + 4];
        float4 d0 = *(const float4*)&g_adst1[dst[k] * 8];
        float4 d1 = *(const float4*)&g_adst1[dst[k] * 8 + 4];
        uint4 w;
        w.x = exp2_h2(lrelu(s0.x + d0.x), lrelu(s0.y + d0.y));
        w.y = exp2_h2(lrelu(s0.z + d0.z), lrelu(s0.w + d0.w));
        w.z = exp2_h2(lrelu(s1.x + d1.x), lrelu(s1.y + d1.y));
        w.w = exp2_h2(lrelu(s1.z + d1.z), lrelu(s1.w + d1.w));
        *(uint4*)&g_ewh[(size_t)p * 8] = w;
    }
}

// -------- tensor-core GEMM1 + fused attention coefs (single-phase loads) --------
__global__ __launch_bounds__(256, 2)
void gemm1_tc_kernel(const float* __restrict__ asv,
                     const float* __restrict__ adv) {
    __shared__ __half Xs[128][136];  // full K=128, pad 8: LDSM conflict-free
    __shared__ __half Ws[128][72];   // full K rows x 64 cols
    __shared__ float sa[64], sd[64];
    int t = threadIdx.x, lane = t & 31, wid = t >> 5;
    int nb = blockIdx.x;             // head / 64-col block
    int mb = blockIdx.y;
    int mB = mb * 128;
    if (t < 64) { sa[t] = asv[nb * 64 + t]; sd[t] = adv[nb * 64 + t]; }

    #pragma unroll
    for (int p = 0; p < 8; p++) {
        int idx = t + p * 256;           // 0..2047
        int row = idx >> 4, ch = idx & 15;
        int grow = mB + row;
        uint4 v = make_uint4(0u, 0u, 0u, 0u);
        if (grow < NN)
            v = *(const uint4*)&g_xh[(size_t)grow * FIN + ch * 8];
        *(uint4*)&Xs[row][ch * 8] = v;
    }
    #pragma unroll
    for (int p = 0; p < 4; p++) {
        int idx = t + p * 256;           // 0..1023
        int row = idx >> 3, ch = idx & 7;
        uint4 v = *(const uint4*)&g_w1h[(size_t)row * D1 + nb * 64 + ch * 8];
        *(uint4*)&Ws[row][ch * 8] = v;
    }
    __syncthreads();

    float acc[8][4];
    #pragma unroll
    for (int i = 0; i < 8; i++)
        #pragma unroll
        for (int j = 0; j < 4; j++) acc[i][j] = 0.f;

    #pragma unroll
    for (int ks = 0; ks < 8; ks++) {
        int k0 = ks * 16;
        uint32_t a0, a1, a2, a3;
        {
            uint32_t ad = sptr(&Xs[wid * 16 + (lane & 15)][k0 + ((lane & 16) ? 8 : 0)]);
            asm volatile(
                "ldmatrix.sync.aligned.m8n8.x4.shared.b16 {%0,%1,%2,%3}, [%4];"
                : "=r"(a0), "=r"(a1), "=r"(a2), "=r"(a3) : "r"(ad));
        }
        #pragma unroll
        for (int ntp = 0; ntp < 4; ntp++) {
            uint32_t b0, b1, b2, b3;
            uint32_t bd = sptr(&Ws[k0 + (lane & 15)][ntp * 16 + ((lane & 16) ? 8 : 0)]);
            asm volatile(
                "ldmatrix.sync.aligned.m8n8.x4.trans.shared.b16 {%0,%1,%2,%3}, [%4];"
                : "=r"(b0), "=r"(b1), "=r"(b2), "=r"(b3) : "r"(bd));
            asm volatile(
                "mma.sync.aligned.m16n8k16.row.col.f32.f16.f16.f32 "
                "{%0,%1,%2,%3}, {%4,%5,%6,%7}, {%8,%9}, {%0,%1,%2,%3};"
                : "+f"(acc[2 * ntp][0]), "+f"(acc[2 * ntp][1]),
                  "+f"(acc[2 * ntp][2]), "+f"(acc[2 * ntp][3])
                : "r"(a0), "r"(a1), "r"(a2), "r"(a3), "r"(b0), "r"(b1));
            asm volatile(
                "mma.sync.aligned.m16n8k16.row.col.f32.f16.f16.f32 "
                "{%0,%1,%2,%3}, {%4,%5,%6,%7}, {%8,%9}, {%0,%1,%2,%3};"
                : "+f"(acc[2 * ntp + 1][0]), "+f"(acc[2 * ntp + 1][1]),
                  "+f"(acc[2 * ntp + 1][2]), "+f"(acc[2 * ntp + 1][3])
                : "r"(a0), "r"(a1), "r"(a2), "r"(a3), "r"(b2), "r"(b3));
        }
    }

    // epilogue: store h1 fp16 + complete per-head coefs (BN==HID)
    int rlo = mB + wid * 16 + (lane >> 2);
    int rhi = rlo + 8;
    int q = lane & 3;
    float slo = 0.f, shi = 0.f, dlo = 0.f, dhi = 0.f;
    #pragma unroll
    for (int nt = 0; nt < 8; nt++) {
        int c = nt * 8 + 2 * q;
        slo += acc[nt][0] * sa[c] + acc[nt][1] * sa[c + 1];
        dlo += acc[nt][0] * sd[c] + acc[nt][1] * sd[c + 1];
        shi += acc[nt][2] * sa[c] + acc[nt][3] * sa[c + 1];
        dhi += acc[nt][2] * sd[c] + acc[nt][3] * sd[c + 1];
        if (rlo < NN)
            *(__half2*)&g_h1h[(size_t)rlo * D1 + nb * 64 + c] =
                __floats2half2_rn(acc[nt][0], acc[nt][1]);
        if (rhi < NN)
            *(__half2*)&g_h1h[(size_t)rhi * D1 + nb * 64 + c] =
                __floats2half2_rn(acc[nt][2], acc[nt][3]);
    }
    #pragma unroll
    for (int o = 1; o <= 2; o <<= 1) {
        slo += __shfl_xor_sync(0xffffffffu, slo, o);
        dlo += __shfl_xor_sync(0xffffffffu, dlo, o);
        shi += __shfl_xor_sync(0xffffffffu, shi, o);
        dhi += __shfl_xor_sync(0xffffffffu, dhi, o);
    }
    if (q == 0) {
        if (rlo < NN) { g_asrc1[rlo * 8 + nb] = slo; g_adst1[rlo * 8 + nb] = dlo; }
        if (rhi < NN) { g_asrc1[rhi * 8 + nb] = shi; g_adst1[rhi * 8 + nb] = dhi; }
    }
}

// -------- layer-1 aggregation: direct loads, 8 channels/thread --------
// 4 nodes per 256-thread block, 64 threads/node; thread t owns channels
// 8t..8t+7 (all in head t>>3). Per edge: broadcast index + scalar weight +
// ONE LDG.128 gather. No smem, no barriers, no shuffles.
__global__ void agg1_kernel(const float* __restrict__ b1) {
    int tt = threadIdx.x;
    int t = tt & 63;
    int d = blockIdx.x * 4 + (tt >> 6);   // NN % 4 == 0
    int beg = g_rowptr[d];
    int end = g_rowptr[d + 1];
    int h8 = t >> 3;                      // head of channels 8t..8t+7
    float acc[8];
    #pragma unroll
    for (int j = 0; j < 8; j++) acc[j] = 0.f;
    float wsum = 0.f;

    #pragma unroll 4
    for (int i = beg; i < end; i++) {
        int sn = g_csrc[i];                                   // broadcast
        float a = __half2float(g_ewh[(size_t)i * 8 + h8]);    // 4 addrs/warp
        union { uint4 u; __half2 h[4]; } v;
        v.u = *(const uint4*)&g_h1h[(size_t)sn * D1 + 8 * t]; // LDG.128
        #pragma unroll
        for (int j = 0; j < 4; j++) {
            float2 f = __half22float2(v.h[j]);
            acc[2 * j]     += a * f.x;
            acc[2 * j + 1] += a * f.y;
        }
        wsum += a;
    }
    float inv = 1.f / (wsum + 1e-16f);
    float4 bv0 = *(const float4*)&b1[8 * t];
    float4 bv1 = *(const float4*)&b1[8 * t + 4];
    float o[8];
    o[0] = acc[0] * inv + bv0.x;
    o[1] = acc[1] * inv + bv0.y;
    o[2] = acc[2] * inv + bv0.z;
    o[3] = acc[3] * inv + bv0.w;
    o[4] = acc[4] * inv + bv1.x;
    o[5] = acc[5] * inv + bv1.y;
    o[6] = acc[6] * inv + bv1.z;
    o[7] = acc[7] * inv + bv1.w;
    #pragma unroll
    for (int j = 0; j < 8; j++) o[j] = o[j] > 0.f ? o[j] : expm1f(o[j]);
    union { uint4 u; __half2 h[4]; } pk;
    #pragma unroll
    for (int j = 0; j < 4; j++)
        pk.h[j] = __floats2half2_rn(o[2 * j], o[2 * j + 1]);
    *(uint4*)&g_h1act[(size_t)d * D1 + 8 * t] = pk.u;         // STG.128
}

// -------- layer 2 GEMV + coefficients (warp per node, transposed W2 smem) --------
__global__ void node2_kernel(const float* __restrict__ W2,
                             const float* __restrict__ as2,
                             const float* __restrict__ ad2) {
    __shared__ float Ws[NC * D1];   // [j][c] transposed
    __shared__ float sas[NC], sad[NC];
    int t = threadIdx.x;
    for (int i = t; i < D1 * NC; i += 256) {
        int c = i / NC, j = i - c * NC;
        Ws[j * D1 + c] = W2[i];
    }
    if (t < NC) { sas[t] = as2[t]; sad[t] = ad2[t]; }
    __syncthreads();
    int n = blockIdx.x * 8 + (t >> 5);
    if (n >= NN) return;
    int lane = t & 31;
    const __half* hp = &g_h1act[(size_t)n * D1];
    float acc[NC];
    #pragma unroll
    for (int j = 0; j < NC; j++) acc[j] = 0.f;
    for (int c = lane; c < D1; c += 32) {
        float xv = __half2float(hp[c]);
        #pragma unroll
        for (int j = 0; j < NC; j++) acc[j] += xv * Ws[j * D1 + c];
    }
    #pragma unroll
    for (int j = 0; j < NC; j++) acc[j] = wredsum(acc[j]);
    if (lane == 0) {
        float s = 0.f, dd = 0.f;
        #pragma unroll
        for (int j = 0; j < NC; j++) {
            g_h2[n * NC + j] = acc[j];
            s  += acc[j] * sas[j];
            dd += acc[j] * sad[j];
        }
        g_asrc2[n] = s;
        g_adst2[n] = dd;
    }
}

// -------- layer-2 edge softmax + aggregation (warp per dst, single pass) --------
__global__ void agg2_kernel(const float* __restrict__ b2) {
    int n = blockIdx.x * 8 + (threadIdx.x >> 5);
    if (n >= NN) return;
    int lane = threadIdx.x & 31;
    int beg = g_rowptr[n], end = g_rowptr[n + 1];
    float adv = g_adst2[n];
    float s = 0.f;
    float acc[NC];
    #pragma unroll
    for (int j = 0; j < NC; j++) acc[j] = 0.f;
    for (int i = beg + lane; i < end; i += 32) {
        int sn = g_csrc[i];
        float e = g_asrc2[sn] + adv;
        e = e > 0.f ? e : 0.2f * e;
        float w = __expf(e);
        s += w;
        const float* hp = &g_h2[sn * NC];
        #pragma unroll
        for (int j = 0; j < NC; j++) acc[j] += w * hp[j];
    }
    s = wredsum(s);
    #pragma unroll
    for (int j = 0; j < NC; j++) acc[j] = wredsum(acc[j]);
    if (lane == 0) {
        float inv = 1.f / (s + 1e-16f);
        #pragma unroll
        for (int j = 0; j < NC; j++)
            g_agg2[n * NC + j] = acc[j] * inv + b2[j];
    }
}

// -------- mean pooling per graph (batch is sorted) --------
__global__ void pool_kernel(const int* __restrict__ batch,
                            float* __restrict__ out) {
    int g = blockIdx.x;
    int t = threadIdx.x;
    int lo, hi;
    { int a = 0, b = NN;
      while (a < b) { int mid = (a + b) >> 1; if (batch[mid] < g) a = mid + 1; else b = mid; }
      lo = a; }
    { int a = lo, b = NN;
      while (a < b) { int mid = (a + b) >> 1; if (batch[mid] < g + 1) a = mid + 1; else b = mid; }
      hi = a; }
    __shared__ float red[NC];
    if (t < NC) red[t] = 0.f;
    __syncthreads();
    float acc[NC];
    #pragma unroll
    for (int j = 0; j < NC; j++) acc[j] = 0.f;
    for (int i = lo + t; i < hi; i += 256) {
        const float* hp = &g_agg2[i * NC];
        #pragma unroll
        for (int j = 0; j < NC; j++) acc[j] += hp[j];
    }
    #pragma unroll
    for (int j = 0; j < NC; j++) atomicAdd(&red[j], acc[j]);
    __syncthreads();
    int cnt = hi - lo;
    if (cnt < 1) cnt = 1;
    if (t < NC) out[g * NC + t] = red[t] / (float)cnt;
}

// -------- launcher (gemm1_tc at launch idx 3 for profiling) --------
extern "C" void kernel_launch(void* const* d_in, const int* in_sizes, int n_in,
                              void* d_out, int out_size) {
    const float* x   = (const float*)d_in[0];
    const int*   ei  = (const int*)d_in[1];
    const int*   bat = (const int*)d_in[2];
    const float* W1  = (const float*)d_in[3];
    const float* as1 = (const float*)d_in[4];
    const float* ad1 = (const float*)d_in[5];
    const float* b1  = (const float*)d_in[6];
    const float* W2  = (const float*)d_in[7];
    const float* as2 = (const float*)d_in[8];
    const float* ad2 = (const float*)d_in[9];
    const float* b2  = (const float*)d_in[10];
    float* out = (float*)d_out;

    prep_kernel<<<(NN * FIN / 4 + 255) / 256, 256>>>(x, W1, ei);
    scanA_kernel<<<NB, 256>>>();
    scanB_kernel<<<1, 128>>>();
    gemm1_tc_kernel<<<dim3(HEADS, (NN + 127) / 128), 256>>>(as1, ad1);
    scanC_kernel<<<(NN + 255) / 256, 256>>>();
    scatter_ew_kernel<<<(EE / 4 + 255) / 256, 256>>>(ei);

    agg1_kernel<<<NN / 4, 256>>>(b1);

    node2_kernel<<<(NN + 7) / 8, 256>>>(W2, as2, ad2);
    agg2_kernel<<<(NN + 7) / 8, 256>>>(b2);
    pool_kernel<<<NG, 256>>>(bat, out);
}